// round 14
// baseline (speedup 1.0000x reference)
#include <cuda_runtime.h>
#include <cuda_fp16.h>
#include <stdint.h>

#define TILE     192
#define MTHREADS 384
#define EXROW    272                    // exchange row stride bytes (136 halves)

// -------- device-global scratch --------
__device__ __half g_fm[349440 * 16];    // interleaved [texel][16] fp16, gain folded (11.2 MB)
__device__ __half g_w0[96 * 128];       // [k][n] fp16, 16B-chunk XOR-swizzled
__device__ __half g_w1[128 * 128];
__device__ __half g_w2[128 * 128];
__device__ __half g_w3[128 * 8];        // linear, cols 3..7 zero-padded
__device__ uint4  g_act[5462 * 2304];   // staged features: [tile][chunk c=0..11][point p=0..191] 16B

__constant__ int c_loff[6] = {0, 256, 1280, 5376, 21760, 87296};

__device__ __forceinline__ int wswz(int k, int n) {
    return k * 128 + ((((n >> 3) ^ (k & 7))) << 3) + (n & 7);
}

// =====================================================================
// Prep: fm interleave (fp16) + weight transpose/swizzle
// =====================================================================
__global__ void prep_all(const float* __restrict__ f0, const float* __restrict__ f1,
                         const float* __restrict__ f2, const float* __restrict__ f3,
                         const float* __restrict__ f4, const float* __restrict__ f5,
                         const float* __restrict__ lg,
                         const float* __restrict__ w0, const float* __restrict__ w1,
                         const float* __restrict__ w2, const float* __restrict__ w3)
{
    int idx = blockIdx.x * blockDim.x + threadIdx.x;
    if (idx < 349440) {
        int tex = idx;
        int lod; const float* f;
        if      (tex < 256)   { lod = 0; f = f0; }
        else if (tex < 1280)  { lod = 1; f = f1; }
        else if (tex < 5376)  { lod = 2; f = f2; }
        else if (tex < 21760) { lod = 3; f = f3; }
        else if (tex < 87296) { lod = 4; f = f4; }
        else                  { lod = 5; f = f5; }
        int local = tex - c_loff[lod];
        int ss = 1 << (2 * (4 + lod));
        float gain = exp2f(lg[lod]);
        __half h[16];
#pragma unroll
        for (int c = 0; c < 16; c++) h[c] = __float2half(f[c * ss + local] * gain);
        uint4* dst = reinterpret_cast<uint4*>(g_fm + tex * 16);
        dst[0] = *reinterpret_cast<uint4*>(&h[0]);
        dst[1] = *reinterpret_cast<uint4*>(&h[8]);
        return;
    }
    int i = idx - 349440;
    if (i < 12288) {
        int n = i & 127, k = i >> 7;
        g_w0[wswz(k, n)] = __float2half(w0[n * 96 + k]);
    } else if (i < 28672) {
        int j = i - 12288; int n = j & 127, k = j >> 7;
        g_w1[wswz(k, n)] = __float2half(w1[n * 128 + k]);
    } else if (i < 45056) {
        int j = i - 28672; int n = j & 127, k = j >> 7;
        g_w2[wswz(k, n)] = __float2half(w2[n * 128 + k]);
    } else if (i < 46080) {
        int j = i - 45056; int n = j & 7, k = j >> 3;
        g_w3[j] = (n < 3) ? __float2half(w3[n * 128 + k]) : __float2half(0.f);
    }
}

// =====================================================================
// Gather kernel: block = 384 threads = 192 points x 2 hf; one tile/block.
// Writes tile-blocked [c][p] 16B chunks, fully coalesced.
// =====================================================================
__global__ void __launch_bounds__(384, 4) gather_k(
    const float2* __restrict__ coords, int npts)
{
    int tile = blockIdx.x;
    int t = threadIdx.x;
    int pl = t >> 1;                 // 0..191 point within tile
    int hf = t & 1;
    int p  = tile * TILE + pl;
    uint4* dst = g_act + tile * 2304;

    if (p >= npts) {
        uint4 z = make_uint4(0, 0, 0, 0);
#pragma unroll
        for (int lod = 0; lod < 6; lod++) dst[(lod * 2 + hf) * 192 + pl] = z;
        return;
    }
    float2 g = coords[p];
    float gx = (g.x + 1.f) * 0.5f;
    float gy = (g.y + 1.f) * 0.5f;
#pragma unroll
    for (int lod = 0; lod < 6; lod++) {
        const int sl = 4 + lod;
        const int s  = 1 << sl;
        const float sm1 = (float)(s - 1);
        float fx = fminf(fmaxf(gx * sm1, 0.f), sm1);
        float fy = fminf(fmaxf(gy * sm1, 0.f), sm1);
        float x0f = floorf(fx), y0f = floorf(fy);
        int   x0 = (int)x0f, y0 = (int)y0f;
        float wx = fx - x0f, wy = fy - y0f;
        int   x1 = min(x0 + 1, s - 1);
        int   y1 = min(y0 + 1, s - 1);
        float w00 = (1.f - wx) * (1.f - wy), w10 = wx * (1.f - wy);
        float w01 = (1.f - wx) * wy,         w11 = wx * wy;
        const char* fmb = (const char*)g_fm + (hf << 4);
        uint4 t00 = *(const uint4*)(fmb + ((uint32_t)(c_loff[lod] + ((y0 << sl) + x0)) << 5));
        uint4 t10 = *(const uint4*)(fmb + ((uint32_t)(c_loff[lod] + ((y0 << sl) + x1)) << 5));
        uint4 t01 = *(const uint4*)(fmb + ((uint32_t)(c_loff[lod] + ((y1 << sl) + x0)) << 5));
        uint4 t11 = *(const uint4*)(fmb + ((uint32_t)(c_loff[lod] + ((y1 << sl) + x1)) << 5));
        const __half2* h00 = reinterpret_cast<const __half2*>(&t00);
        const __half2* h10 = reinterpret_cast<const __half2*>(&t10);
        const __half2* h01 = reinterpret_cast<const __half2*>(&t01);
        const __half2* h11 = reinterpret_cast<const __half2*>(&t11);
        uint4 res;
        __half2* ro = reinterpret_cast<__half2*>(&res);
#pragma unroll
        for (int e = 0; e < 4; e++) {
            float2 a = __half22float2(h00[e]);
            float2 b = __half22float2(h10[e]);
            float2 c = __half22float2(h01[e]);
            float2 d = __half22float2(h11[e]);
            float rx = a.x * w00 + b.x * w10 + c.x * w01 + d.x * w11;
            float ry = a.y * w00 + b.y * w10 + c.y * w01 + d.y * w11;
            ro[e] = __floats2half2_rn(rx, ry);
        }
        dst[(lod * 2 + hf) * 192 + pl] = res;
    }
}

// =====================================================================
__device__ __forceinline__ uint32_t smem_u32(const void* p) {
    return (uint32_t)__cvta_generic_to_shared(p);
}

__device__ __forceinline__ void mma_16816(float* c, uint32_t a0, uint32_t a1, uint32_t a2, uint32_t a3,
                                          uint32_t b0, uint32_t b1) {
    asm volatile(
        "mma.sync.aligned.m16n8k16.row.col.f32.f16.f16.f32 "
        "{%0,%1,%2,%3},{%4,%5,%6,%7},{%8,%9},{%0,%1,%2,%3};\n"
        : "+f"(c[0]), "+f"(c[1]), "+f"(c[2]), "+f"(c[3])
        : "r"(a0), "r"(a1), "r"(a2), "r"(a3), "r"(b0), "r"(b1));
}

__device__ __forceinline__ uint32_t pack_relu(float x, float y) {
    __half2 h = __floats2half2_rn(fmaxf(x, 0.f), fmaxf(y, 0.f));
    return *reinterpret_cast<uint32_t*>(&h);
}

__device__ __forceinline__ void sts_u32(uint32_t addr, uint32_t v) {
    asm volatile("st.shared.u32 [%0], %1;" :: "r"(addr), "r"(v) : "memory");
}

// ---------------- SMEM layout (bytes) ----------------
#define S_ACT   0                        // 2 x 36864 (double-buffered [c][p] tile)
#define S_EXCH  73728                    // 6 pairs x 32 rows x 272B = 52224
#define S_W     125952                   // 92160
#define S_BIAS  218112                   // 392 floats
#define SMEM_BYTES 219712

// =====================================================================
// MLP persistent kernel: 384 threads = 12 warps = 6 pairs; TILE=192.
// Pair P owns rows [P*32,+32); warp sub computes n-cols [sub*64,+64).
// Register-resident activations; single exchange buffer (2 pair-bars/layer);
// act tile double-buffered with 1-tile global prefetch.
// =====================================================================
__global__ void __launch_bounds__(MTHREADS, 1) enc_mlp(
    const float* __restrict__ b0, const float* __restrict__ b1,
    const float* __restrict__ b2, const float* __restrict__ b3,
    float* __restrict__ out, int ntiles, int npts)
{
    extern __shared__ __align__(16) char sm[];
    uint4*  actb = reinterpret_cast<uint4*>(sm + S_ACT);     // [2][2304]
    __half* w0s  = reinterpret_cast<__half*>(sm + S_W);
    __half* w1s  = w0s + 12288;
    __half* w2s  = w1s + 16384;
    __half* w3s  = w2s + 16384;
    float*  bs   = reinterpret_cast<float*>(sm + S_BIAS);

    int tid = threadIdx.x;

    // ---- stage weights + biases ----
    {
        uint4* dw = (uint4*)w0s;
        const uint4* s0 = (const uint4*)g_w0;
        for (int i = tid; i < 12288 / 8; i += MTHREADS) dw[i] = s0[i];
        const uint4* s1 = (const uint4*)g_w1;
        for (int i = tid; i < 16384 / 8; i += MTHREADS) dw[1536 + i] = s1[i];
        const uint4* s2 = (const uint4*)g_w2;
        for (int i = tid; i < 16384 / 8; i += MTHREADS) dw[3584 + i] = s2[i];
        const uint4* s3 = (const uint4*)g_w3;
        for (int i = tid; i < 1024 / 8;  i += MTHREADS) dw[5632 + i] = s3[i];
        for (int i = tid; i < 128; i += MTHREADS) {
            bs[i] = b0[i]; bs[128 + i] = b1[i]; bs[256 + i] = b2[i];
        }
        if (tid < 8) bs[384 + tid] = (tid < 3) ? b3[tid] : 0.f;
    }
    // ---- stage first tile into buf0 ----
    {
        const uint4* src = g_act + (size_t)blockIdx.x * 2304;
#pragma unroll
        for (int j = 0; j < 6; j++) actb[tid + j * 384] = src[tid + j * 384];
    }
    __syncthreads();

    int wid = tid >> 5, lane = tid & 31;
    const int pairP = wid >> 1, sub = wid & 1;
    const int cb = (lane & 3) * 2;
    const int cp = lane >> 4;
    const int xorv = lane & 7;
    const int nbase = sub * 64;
    uint32_t wb0 = smem_u32(w0s) + ((lane & 15) << 8);
    uint32_t wb1 = smem_u32(w1s) + ((lane & 15) << 8);
    uint32_t wb2 = smem_u32(w2s) + ((lane & 15) << 8);
    uint32_t wb3 = smem_u32(w3s) + ((lane & 15) << 4);
    uint32_t exch_b = smem_u32(sm + S_EXCH) + pairP * (32 * EXROW);
    uint32_t stsb = exch_b + (lane >> 2) * EXROW + sub * 128 + cb * 2;
    uint32_t prdb = exch_b + (lane & 15) * EXROW + (1 - sub) * 128 + ((lane >> 4) << 4);
    const uint32_t kofs_own  = (uint32_t)sub << 14;
    const uint32_t kofs_part = (uint32_t)(1 - sub) << 14;
    const int barP = 1 + pairP;
    float* redw = (float*)(sm + S_EXCH + pairP * (32 * EXROW) + (1 - sub) * (16 * EXROW)) + lane * 4;
    float* redr = (float*)(sm + S_EXCH + pairP * (32 * EXROW) + sub       * (16 * EXROW)) + lane * 4;
    // A base within act tile ([c][p] layout): + (lane>>4)*3072 selects k-half chunk
    uint32_t abrel = (uint32_t)((pairP * 32 + (lane & 15)) * 16 + (lane >> 4) * 3072);

    float    c[2][8][4];
    uint32_t hown[2][4][4];

    int li = 0;
    for (int tile = blockIdx.x; tile < ntiles; tile += gridDim.x, li++) {
        int buf = li & 1;
        uint32_t ab = smem_u32(actb + buf * 2304) + abrel;
        // prefetch next tile (regs)
        int ntile = tile + gridDim.x;
        bool hn = ntile < ntiles;
        uint4 pf[6];
        if (hn) {
            const uint4* src = g_act + (size_t)ntile * 2304;
#pragma unroll
            for (int j = 0; j < 6; j++) pf[j] = src[tid + j * 384];
        }

        // ---------- layer 0: 96 -> 128 ----------
#pragma unroll
        for (int n8 = 0; n8 < 8; n8++) {
            float2 bv = *reinterpret_cast<const float2*>(bs + nbase + n8 * 8 + cb);
#pragma unroll
            for (int mt = 0; mt < 2; mt++) {
                c[mt][n8][0] = bv.x; c[mt][n8][1] = bv.y;
                c[mt][n8][2] = bv.x; c[mt][n8][3] = bv.y;
            }
        }
#pragma unroll
        for (int kt = 0; kt < 6; kt++) {
            uint32_t A[2][4];
#pragma unroll
            for (int mt = 0; mt < 2; mt++)
                asm volatile("ldmatrix.sync.aligned.m8n8.x4.shared.b16 {%0,%1,%2,%3}, [%4];\n"
                             : "=r"(A[mt][0]), "=r"(A[mt][1]), "=r"(A[mt][2]), "=r"(A[mt][3])
                             : "r"(ab + mt * 256 + kt * 6144));
#pragma unroll
            for (int j = 0; j < 4; j++) {
                int chunk = sub * 8 + 2 * j + cp;
                uint32_t baddr = wb0 + (kt << 12) + ((uint32_t)(chunk ^ xorv) << 4);
                uint32_t b[4];
                asm volatile("ldmatrix.sync.aligned.m8n8.x4.trans.shared.b16 {%0,%1,%2,%3}, [%4];\n"
                             : "=r"(b[0]), "=r"(b[1]), "=r"(b[2]), "=r"(b[3]) : "r"(baddr));
#pragma unroll
                for (int mt = 0; mt < 2; mt++) {
                    mma_16816(c[mt][2 * j + 0], A[mt][0], A[mt][1], A[mt][2], A[mt][3], b[0], b[1]);
                    mma_16816(c[mt][2 * j + 1], A[mt][0], A[mt][1], A[mt][2], A[mt][3], b[2], b[3]);
                }
            }
        }
        // store prefetched tile into other buffer (safe: prior reads of it ended before
        // this iteration's opening __syncthreads)
        if (hn) {
            uint4* nb = actb + (buf ^ 1) * 2304;
#pragma unroll
            for (int j = 0; j < 6; j++) nb[tid + j * 384] = pf[j];
        }

        // ---------- layers 1,2: own-half before pair bar, partner streamed after ----------
#pragma unroll 1
        for (int layer = 1; layer <= 2; layer++) {
#pragma unroll
            for (int mt = 0; mt < 2; mt++)
#pragma unroll
                for (int t = 0; t < 4; t++) {
                    uint32_t v0 = pack_relu(c[mt][2 * t][0],     c[mt][2 * t][1]);
                    uint32_t v1 = pack_relu(c[mt][2 * t][2],     c[mt][2 * t][3]);
                    uint32_t v2 = pack_relu(c[mt][2 * t + 1][0], c[mt][2 * t + 1][1]);
                    uint32_t v3 = pack_relu(c[mt][2 * t + 1][2], c[mt][2 * t + 1][3]);
                    hown[mt][t][0] = v0; hown[mt][t][1] = v1;
                    hown[mt][t][2] = v2; hown[mt][t][3] = v3;
                    uint32_t sa = stsb + mt * (16 * EXROW) + t * 32;
                    sts_u32(sa, v0);
                    sts_u32(sa + 8 * EXROW, v1);
                    sts_u32(sa + 16, v2);
                    sts_u32(sa + 8 * EXROW + 16, v3);
                }
            const float* bias = bs + layer * 128;
            uint32_t wb = (layer == 1) ? wb1 : wb2;
#pragma unroll
            for (int n8 = 0; n8 < 8; n8++) {
                float2 bv = *reinterpret_cast<const float2*>(bias + nbase + n8 * 8 + cb);
#pragma unroll
                for (int mt = 0; mt < 2; mt++) {
                    c[mt][n8][0] = bv.x; c[mt][n8][1] = bv.y;
                    c[mt][n8][2] = bv.x; c[mt][n8][3] = bv.y;
                }
            }
            // own k-half (registers) — hides partner STS
#pragma unroll
            for (int ktl = 0; ktl < 4; ktl++) {
#pragma unroll
                for (int j = 0; j < 4; j++) {
                    int chunk = sub * 8 + 2 * j + cp;
                    uint32_t cofs = (uint32_t)(chunk ^ xorv) << 4;
                    uint32_t b[4];
                    asm volatile("ldmatrix.sync.aligned.m8n8.x4.trans.shared.b16 {%0,%1,%2,%3}, [%4];\n"
                                 : "=r"(b[0]), "=r"(b[1]), "=r"(b[2]), "=r"(b[3])
                                 : "r"(wb + kofs_own + (ktl << 12) + cofs));
#pragma unroll
                    for (int mt = 0; mt < 2; mt++) {
                        mma_16816(c[mt][2 * j + 0], hown[mt][ktl][0], hown[mt][ktl][1], hown[mt][ktl][2], hown[mt][ktl][3], b[0], b[1]);
                        mma_16816(c[mt][2 * j + 1], hown[mt][ktl][0], hown[mt][ktl][1], hown[mt][ktl][2], hown[mt][ktl][3], b[2], b[3]);
                    }
                }
            }
            asm volatile("bar.sync %0, 64;" :: "r"(barP) : "memory");
            // partner k-half streamed
#pragma unroll
            for (int ktl = 0; ktl < 4; ktl++) {
                uint32_t hp0[4], hp1[4];
                asm volatile("ldmatrix.sync.aligned.m8n8.x4.shared.b16 {%0,%1,%2,%3}, [%4];\n"
                             : "=r"(hp0[0]), "=r"(hp0[1]), "=r"(hp0[2]), "=r"(hp0[3])
                             : "r"(prdb + ktl * 32));
                asm volatile("ldmatrix.sync.aligned.m8n8.x4.shared.b16 {%0,%1,%2,%3}, [%4];\n"
                             : "=r"(hp1[0]), "=r"(hp1[1]), "=r"(hp1[2]), "=r"(hp1[3])
                             : "r"(prdb + 16 * EXROW + ktl * 32));
#pragma unroll
                for (int j = 0; j < 4; j++) {
                    int chunk = sub * 8 + 2 * j + cp;
                    uint32_t cofs = (uint32_t)(chunk ^ xorv) << 4;
                    uint32_t b[4];
                    asm volatile("ldmatrix.sync.aligned.m8n8.x4.trans.shared.b16 {%0,%1,%2,%3}, [%4];\n"
                                 : "=r"(b[0]), "=r"(b[1]), "=r"(b[2]), "=r"(b[3])
                                 : "r"(wb + kofs_part + (ktl << 12) + cofs));
                    mma_16816(c[0][2 * j + 0], hp0[0], hp0[1], hp0[2], hp0[3], b[0], b[1]);
                    mma_16816(c[0][2 * j + 1], hp0[0], hp0[1], hp0[2], hp0[3], b[2], b[3]);
                    mma_16816(c[1][2 * j + 0], hp1[0], hp1[1], hp1[2], hp1[3], b[0], b[1]);
                    mma_16816(c[1][2 * j + 1], hp1[0], hp1[1], hp1[2], hp1[3], b[2], b[3]);
                }
            }
            asm volatile("bar.sync %0, 64;" :: "r"(barP) : "memory");  // partner reads done (WAR for next STS)
        }

        // ---------- out layer: partial-k both m-tiles + pair reduction ----------
#pragma unroll
        for (int mt = 0; mt < 2; mt++)
#pragma unroll
            for (int t = 0; t < 4; t++) {
                hown[mt][t][0] = pack_relu(c[mt][2 * t][0],     c[mt][2 * t][1]);
                hown[mt][t][1] = pack_relu(c[mt][2 * t][2],     c[mt][2 * t][3]);
                hown[mt][t][2] = pack_relu(c[mt][2 * t + 1][0], c[mt][2 * t + 1][1]);
                hown[mt][t][3] = pack_relu(c[mt][2 * t + 1][2], c[mt][2 * t + 1][3]);
            }
        float c3[2][4];
#pragma unroll
        for (int mt = 0; mt < 2; mt++) { c3[mt][0] = 0.f; c3[mt][1] = 0.f; c3[mt][2] = 0.f; c3[mt][3] = 0.f; }
#pragma unroll
        for (int ktl = 0; ktl < 4; ktl++) {
            uint32_t b0r, b1r;
            asm volatile("ldmatrix.sync.aligned.m8n8.x2.trans.shared.b16 {%0,%1}, [%2];\n"
                         : "=r"(b0r), "=r"(b1r)
                         : "r"(wb3 + (uint32_t)(sub * 4 + ktl) * 256));
            mma_16816(c3[0], hown[0][ktl][0], hown[0][ktl][1], hown[0][ktl][2], hown[0][ktl][3], b0r, b1r);
            mma_16816(c3[1], hown[1][ktl][0], hown[1][ktl][1], hown[1][ktl][2], hown[1][ktl][3], b0r, b1r);
        }
        *(float4*)redw = make_float4(c3[1 - sub][0], c3[1 - sub][1], c3[1 - sub][2], c3[1 - sub][3]);
        asm volatile("bar.sync %0, 64;" :: "r"(barP) : "memory");
        float4 pr = *(const float4*)redr;
        float o0 = c3[sub][0] + pr.x;
        float o1 = c3[sub][1] + pr.y;
        float o2 = c3[sub][2] + pr.z;
        float o3 = c3[sub][3] + pr.w;

        int r = tile * TILE + pairP * 32 + sub * 16 + (lane >> 2);
        if (cb == 0) {
            if (r < npts)     { out[r * 3 + 0] = o0 + bs[384];       out[r * 3 + 1] = o1 + bs[385]; }
            if (r + 8 < npts) { out[(r + 8) * 3 + 0] = o2 + bs[384]; out[(r + 8) * 3 + 1] = o3 + bs[385]; }
        } else if (cb == 2) {
            if (r < npts)     out[r * 3 + 2] = o0 + bs[386];
            if (r + 8 < npts) out[(r + 8) * 3 + 2] = o2 + bs[386];
        }
        __syncthreads();   // all smem reads done; prefetched buffer visible for next iter
    }
}

// =====================================================================
extern "C" void kernel_launch(void* const* d_in, const int* in_sizes, int n_in,
                              void* d_out, int out_size)
{
    const float* xc = (const float*)d_in[0];
    const float* f0 = (const float*)d_in[1];
    const float* f1 = (const float*)d_in[2];
    const float* f2 = (const float*)d_in[3];
    const float* f3 = (const float*)d_in[4];
    const float* f4 = (const float*)d_in[5];
    const float* f5 = (const float*)d_in[6];
    const float* lg = (const float*)d_in[7];
    const float* w0 = (const float*)d_in[8];
    const float* b0 = (const float*)d_in[9];
    const float* w1 = (const float*)d_in[10];
    const float* b1 = (const float*)d_in[11];
    const float* w2 = (const float*)d_in[12];
    const float* b2 = (const float*)d_in[13];
    const float* w3 = (const float*)d_in[14];
    const float* b3 = (const float*)d_in[15];

    int npts   = in_sizes[0] / 2;
    int ntiles = (npts + TILE - 1) / TILE;   // 5462 for 1024x1024

    prep_all<<<(349440 + 46080 + 255) / 256, 256>>>(f0, f1, f2, f3, f4, f5, lg, w0, w1, w2, w3);
    gather_k<<<ntiles, 384>>>((const float2*)xc, npts);

    cudaFuncSetAttribute(enc_mlp, cudaFuncAttributeMaxDynamicSharedMemorySize, SMEM_BYTES);
    int nsm = 0;
    cudaDeviceGetAttribute(&nsm, cudaDevAttrMultiProcessorCount, 0);
    if (nsm <= 0) nsm = 148;

    enc_mlp<<<nsm, MTHREADS, SMEM_BYTES>>>(b0, b1, b2, b3, (float*)d_out, ntiles, npts);
}

// round 16
// speedup vs baseline: 1.0961x; 1.0961x over previous
#include <cuda_runtime.h>
#include <cuda_fp16.h>
#include <stdint.h>

#define THREADS  384
#define TILE     128
#define A0STRIDE 104   // feature tile row stride in halves (208B = 13*16B, conflict-free ldmatrix)

// -------- device-global scratch --------
__device__ __half g_fm[349440 * 16];    // interleaved [texel][16] fp16, gain folded (11.2 MB)
__device__ __half g_w0[96 * 128];       // [k][n] fp16, 16B-chunk XOR-swizzled
__device__ __half g_w1[128 * 128];
__device__ __half g_w2[128 * 128];
__device__ __half g_w3[128 * 8];        // linear, cols 3..7 zero-padded

__constant__ int c_loff[6] = {0, 256, 1280, 5376, 21760, 87296};

__device__ __forceinline__ int wswz(int k, int n) {
    return k * 128 + ((((n >> 3) ^ (k & 7))) << 3) + (n & 7);
}

// =====================================================================
// Prep kernel: fm interleave (fp16) + weight transpose/swizzle
// =====================================================================
__global__ void prep_all(const float* __restrict__ f0, const float* __restrict__ f1,
                         const float* __restrict__ f2, const float* __restrict__ f3,
                         const float* __restrict__ f4, const float* __restrict__ f5,
                         const float* __restrict__ lg,
                         const float* __restrict__ w0, const float* __restrict__ w1,
                         const float* __restrict__ w2, const float* __restrict__ w3)
{
    int idx = blockIdx.x * blockDim.x + threadIdx.x;
    if (idx < 349440) {
        int tex = idx;
        int lod; const float* f;
        if      (tex < 256)   { lod = 0; f = f0; }
        else if (tex < 1280)  { lod = 1; f = f1; }
        else if (tex < 5376)  { lod = 2; f = f2; }
        else if (tex < 21760) { lod = 3; f = f3; }
        else if (tex < 87296) { lod = 4; f = f4; }
        else                  { lod = 5; f = f5; }
        int local = tex - c_loff[lod];
        int ss = 1 << (2 * (4 + lod));
        float gain = exp2f(lg[lod]);
        __half h[16];
#pragma unroll
        for (int c = 0; c < 16; c++) h[c] = __float2half(f[c * ss + local] * gain);
        uint4* dst = reinterpret_cast<uint4*>(g_fm + tex * 16);
        dst[0] = *reinterpret_cast<uint4*>(&h[0]);
        dst[1] = *reinterpret_cast<uint4*>(&h[8]);
        return;
    }
    int i = idx - 349440;
    if (i < 12288) {                         // w0: 96x128 (k x n)
        int n = i & 127, k = i >> 7;
        g_w0[wswz(k, n)] = __float2half(w0[n * 96 + k]);
    } else if (i < 28672) {                  // w1
        int j = i - 12288;
        int n = j & 127, k = j >> 7;
        g_w1[wswz(k, n)] = __float2half(w1[n * 128 + k]);
    } else if (i < 45056) {                  // w2
        int j = i - 28672;
        int n = j & 127, k = j >> 7;
        g_w2[wswz(k, n)] = __float2half(w2[n * 128 + k]);
    } else if (i < 46080) {                  // w3: 128x8, linear, n>=3 zero
        int j = i - 45056;
        int n = j & 7, k = j >> 3;
        g_w3[j] = (n < 3) ? __float2half(w3[n * 128 + k]) : __float2half(0.f);
    }
}

// =====================================================================
__device__ __forceinline__ uint32_t smem_u32(const void* p) {
    return (uint32_t)__cvta_generic_to_shared(p);
}

__device__ __forceinline__ void mma_16816(float* c, uint32_t a0, uint32_t a1, uint32_t a2, uint32_t a3,
                                          uint32_t b0, uint32_t b1) {
    asm volatile(
        "mma.sync.aligned.m16n8k16.row.col.f32.f16.f16.f32 "
        "{%0,%1,%2,%3},{%4,%5,%6,%7},{%8,%9},{%0,%1,%2,%3};\n"
        : "+f"(c[0]), "+f"(c[1]), "+f"(c[2]), "+f"(c[3])
        : "r"(a0), "r"(a1), "r"(a2), "r"(a3), "r"(b0), "r"(b1));
}

__device__ __forceinline__ uint32_t pack_relu(float x, float y) {
    __half2 h = __floats2half2_rn(fmaxf(x, 0.f), fmaxf(y, 0.f));
    return *reinterpret_cast<uint32_t*>(&h);
}

__device__ __forceinline__ void sts_u32(uint32_t addr, uint32_t v) {
    asm volatile("st.shared.u32 [%0], %1;" :: "r"(addr), "r"(v) : "memory");
}

// ---------------- SMEM layout (bytes) ----------------
#define S_ACT0  0                        // 2 x 128 x 104 halves = 53248 B
#define S_EXCH  53248                    // 2 buffers x (4 pairs x 32 rows x 136 halves) = 69632 B
#define EXBUF   34816                    // one exchange buffer
#define S_W     122880                   // 46080 halves = 92160 B
#define S_BIAS  215040                   // 392 floats
#define SMEM_BYTES (215040 + 1600)
#define EXROW    272                     // exchange row stride bytes (136 halves)

// =====================================================================
// 384 threads: warps 0-7 = MLP in pairs. Pair P owns m-rows [P*32,+32);
//   within a pair, warp sub=wid&1 computes n-cols [sub*64,+64) with register acts.
//   Exchange is latency-hidden: own-k-half mma runs BEFORE the pair barrier;
//   partner k-half streamed afterward with per-ktl temporaries.
// warps 8-11 = gather: interpolation results precomputed into REGISTERS before
//   the empty-buffer wait, so only STS sits on the producer->consumer path.
// =====================================================================
__global__ void __launch_bounds__(THREADS, 1) enc_main(
    const float2* __restrict__ coords,
    const float* __restrict__ b0, const float* __restrict__ b1,
    const float* __restrict__ b2, const float* __restrict__ b3,
    float* __restrict__ out, int ntiles)
{
    extern __shared__ __align__(16) char sm[];
    __half* act0 = reinterpret_cast<__half*>(sm + S_ACT0);   // [2][128][104]
    __half* w0s  = reinterpret_cast<__half*>(sm + S_W);
    __half* w1s  = w0s + 12288;
    __half* w2s  = w1s + 16384;
    __half* w3s  = w2s + 16384;
    float*  bs   = reinterpret_cast<float*>(sm + S_BIAS);

    int tid = threadIdx.x;

    // ---- stage weights + biases ----
    {
        uint4* dw = (uint4*)w0s;
        const uint4* s0 = (const uint4*)g_w0;
        for (int i = tid; i < 12288 / 8; i += THREADS) dw[i] = s0[i];
        const uint4* s1 = (const uint4*)g_w1;
        for (int i = tid; i < 16384 / 8; i += THREADS) dw[1536 + i] = s1[i];
        const uint4* s2 = (const uint4*)g_w2;
        for (int i = tid; i < 16384 / 8; i += THREADS) dw[3584 + i] = s2[i];
        const uint4* s3 = (const uint4*)g_w3;
        for (int i = tid; i < 1024 / 8;  i += THREADS) dw[5632 + i] = s3[i];
        for (int i = tid; i < 128; i += THREADS) {
            bs[i] = b0[i]; bs[128 + i] = b1[i]; bs[256 + i] = b2[i];
        }
        if (tid < 8) bs[384 + tid] = (tid < 3) ? b3[tid] : 0.f;
    }
    __syncthreads();

    int wid = tid >> 5, lane = tid & 31;

    if (wid < 8) {
        // ================= MLP warp pairs =================
        const int pairP = wid >> 1, sub = wid & 1;
        const int cb = (lane & 3) * 2;
        const int cp = lane >> 4;
        const int xorv = lane & 7;
        const int nbase = sub * 64;
        uint32_t wb0 = smem_u32(w0s) + ((lane & 15) << 8);
        uint32_t wb1 = smem_u32(w1s) + ((lane & 15) << 8);
        uint32_t wb2 = smem_u32(w2s) + ((lane & 15) << 8);
        uint32_t wb3 = smem_u32(w3s) + ((lane & 15) << 4);
        uint32_t exch_b = smem_u32(sm + S_EXCH) + pairP * (32 * EXROW);
        uint32_t stsb = exch_b + (lane >> 2) * EXROW + sub * 128 + cb * 2;
        uint32_t prdb = exch_b + (lane & 15) * EXROW + (1 - sub) * 128 + ((lane >> 4) << 4);
        const uint32_t kofs_own  = (uint32_t)sub << 14;
        const uint32_t kofs_part = (uint32_t)(1 - sub) << 14;
        const int barP = 6 + pairP;
        float* redw = (float*)(sm + S_EXCH + pairP * (32 * EXROW) + (1 - sub) * (16 * EXROW)) + lane * 4;
        float* redr = (float*)(sm + S_EXCH + pairP * (32 * EXROW) + sub       * (16 * EXROW)) + lane * 4;

        float    c[2][8][4];        // [mt][n8 within n64][frag]
        uint32_t hown[2][4][4];     // own k-half A frags (register reinterpretation)

        int li = 0;
        for (int tile = blockIdx.x; tile < ntiles; tile += gridDim.x, li++) {
            int buf = li & 1;
            asm volatile("bar.sync %0, 384;" :: "r"(2 + buf) : "memory");
            const __half* a0 = act0 + buf * (128 * A0STRIDE);
            uint32_t ab = smem_u32(a0 + (pairP * 32 + (lane & 15)) * A0STRIDE) + ((lane >> 4) << 4);

            // ---------- layer 0: 96 -> 128 (A from act0, this warp's n64) ----------
#pragma unroll
            for (int n8 = 0; n8 < 8; n8++) {
                float2 bv = *reinterpret_cast<const float2*>(bs + nbase + n8 * 8 + cb);
#pragma unroll
                for (int mt = 0; mt < 2; mt++) {
                    c[mt][n8][0] = bv.x; c[mt][n8][1] = bv.y;
                    c[mt][n8][2] = bv.x; c[mt][n8][3] = bv.y;
                }
            }
#pragma unroll
            for (int kt = 0; kt < 6; kt++) {
                uint32_t A[2][4];
#pragma unroll
                for (int mt = 0; mt < 2; mt++)
                    asm volatile("ldmatrix.sync.aligned.m8n8.x4.shared.b16 {%0,%1,%2,%3}, [%4];\n"
                                 : "=r"(A[mt][0]), "=r"(A[mt][1]), "=r"(A[mt][2]), "=r"(A[mt][3])
                                 : "r"(ab + mt * (16 * A0STRIDE * 2) + kt * 32));
#pragma unroll
                for (int j = 0; j < 4; j++) {
                    int chunk = sub * 8 + 2 * j + cp;
                    uint32_t baddr = wb0 + (kt << 12) + ((uint32_t)(chunk ^ xorv) << 4);
                    uint32_t b[4];
                    asm volatile("ldmatrix.sync.aligned.m8n8.x4.trans.shared.b16 {%0,%1,%2,%3}, [%4];\n"
                                 : "=r"(b[0]), "=r"(b[1]), "=r"(b[2]), "=r"(b[3]) : "r"(baddr));
#pragma unroll
                    for (int mt = 0; mt < 2; mt++) {
                        mma_16816(c[mt][2 * j + 0], A[mt][0], A[mt][1], A[mt][2], A[mt][3], b[0], b[1]);
                        mma_16816(c[mt][2 * j + 1], A[mt][0], A[mt][1], A[mt][2], A[mt][3], b[2], b[3]);
                    }
                }
            }
            asm volatile("bar.arrive %0, 384;" :: "r"(4 + buf) : "memory");

            // ---------- layers 1,2: own-half mma BEFORE barrier, partner streamed after ----------
#pragma unroll 1
            for (int layer = 1; layer <= 2; layer++) {
                const uint32_t eoff = (uint32_t)(layer - 1) * EXBUF;
#pragma unroll
                for (int mt = 0; mt < 2; mt++)
#pragma unroll
                    for (int t = 0; t < 4; t++) {
                        uint32_t v0 = pack_relu(c[mt][2 * t][0],     c[mt][2 * t][1]);
                        uint32_t v1 = pack_relu(c[mt][2 * t][2],     c[mt][2 * t][3]);
                        uint32_t v2 = pack_relu(c[mt][2 * t + 1][0], c[mt][2 * t + 1][1]);
                        uint32_t v3 = pack_relu(c[mt][2 * t + 1][2], c[mt][2 * t + 1][3]);
                        hown[mt][t][0] = v0; hown[mt][t][1] = v1;
                        hown[mt][t][2] = v2; hown[mt][t][3] = v3;
                        uint32_t sa = stsb + eoff + mt * (16 * EXROW) + t * 32;
                        sts_u32(sa, v0);
                        sts_u32(sa + 8 * EXROW, v1);
                        sts_u32(sa + 16, v2);
                        sts_u32(sa + 8 * EXROW + 16, v3);
                    }
                const float* bias = bs + layer * 128;
                uint32_t wb = (layer == 1) ? wb1 : wb2;
#pragma unroll
                for (int n8 = 0; n8 < 8; n8++) {
                    float2 bv = *reinterpret_cast<const float2*>(bias + nbase + n8 * 8 + cb);
#pragma unroll
                    for (int mt = 0; mt < 2; mt++) {
                        c[mt][n8][0] = bv.x; c[mt][n8][1] = bv.y;
                        c[mt][n8][2] = bv.x; c[mt][n8][3] = bv.y;
                    }
                }
                // own k-half (registers) — hides partner's STS + barrier
#pragma unroll
                for (int ktl = 0; ktl < 4; ktl++) {
#pragma unroll
                    for (int j = 0; j < 4; j++) {
                        int chunk = sub * 8 + 2 * j + cp;
                        uint32_t cofs = (uint32_t)(chunk ^ xorv) << 4;
                        uint32_t b[4];
                        asm volatile("ldmatrix.sync.aligned.m8n8.x4.trans.shared.b16 {%0,%1,%2,%3}, [%4];\n"
                                     : "=r"(b[0]), "=r"(b[1]), "=r"(b[2]), "=r"(b[3])
                                     : "r"(wb + kofs_own + (ktl << 12) + cofs));
#pragma unroll
                        for (int mt = 0; mt < 2; mt++) {
                            mma_16816(c[mt][2 * j + 0], hown[mt][ktl][0], hown[mt][ktl][1], hown[mt][ktl][2], hown[mt][ktl][3], b[0], b[1]);
                            mma_16816(c[mt][2 * j + 1], hown[mt][ktl][0], hown[mt][ktl][1], hown[mt][ktl][2], hown[mt][ktl][3], b[2], b[3]);
                        }
                    }
                }
                asm volatile("bar.sync %0, 64;" :: "r"(barP) : "memory");
                // partner k-half: per-ktl A temporaries (8 regs live)
#pragma unroll
                for (int ktl = 0; ktl < 4; ktl++) {
                    uint32_t hp0[4], hp1[4];
                    asm volatile("ldmatrix.sync.aligned.m8n8.x4.shared.b16 {%0,%1,%2,%3}, [%4];\n"
                                 : "=r"(hp0[0]), "=r"(hp0[1]), "=r"(hp0[2]), "=r"(hp0[3])
                                 : "r"(prdb + eoff + ktl * 32));
                    asm volatile("ldmatrix.sync.aligned.m8n8.x4.shared.b16 {%0,%1,%2,%3}, [%4];\n"
                                 : "=r"(hp1[0]), "=r"(hp1[1]), "=r"(hp1[2]), "=r"(hp1[3])
                                 : "r"(prdb + eoff + 16 * EXROW + ktl * 32));
#pragma unroll
                    for (int j = 0; j < 4; j++) {
                        int chunk = sub * 8 + 2 * j + cp;
                        uint32_t cofs = (uint32_t)(chunk ^ xorv) << 4;
                        uint32_t b[4];
                        asm volatile("ldmatrix.sync.aligned.m8n8.x4.trans.shared.b16 {%0,%1,%2,%3}, [%4];\n"
                                     : "=r"(b[0]), "=r"(b[1]), "=r"(b[2]), "=r"(b[3])
                                     : "r"(wb + kofs_part + (ktl << 12) + cofs));
                        mma_16816(c[0][2 * j + 0], hp0[0], hp0[1], hp0[2], hp0[3], b[0], b[1]);
                        mma_16816(c[0][2 * j + 1], hp0[0], hp0[1], hp0[2], hp0[3], b[2], b[3]);
                        mma_16816(c[1][2 * j + 0], hp1[0], hp1[1], hp1[2], hp1[3], b[0], b[1]);
                        mma_16816(c[1][2 * j + 1], hp1[0], hp1[1], hp1[2], hp1[3], b[2], b[3]);
                    }
                }
            }

            // ---------- out layer: partial-k for BOTH m-tiles + pair reduction ----------
#pragma unroll
            for (int mt = 0; mt < 2; mt++)
#pragma unroll
                for (int t = 0; t < 4; t++) {
                    hown[mt][t][0] = pack_relu(c[mt][2 * t][0],     c[mt][2 * t][1]);
                    hown[mt][t][1] = pack_relu(c[mt][2 * t][2],     c[mt][2 * t][3]);
                    hown[mt][t][2] = pack_relu(c[mt][2 * t + 1][0], c[mt][2 * t + 1][1]);
                    hown[mt][t][3] = pack_relu(c[mt][2 * t + 1][2], c[mt][2 * t + 1][3]);
                }
            float c3[2][4];
#pragma unroll
            for (int mt = 0; mt < 2; mt++) { c3[mt][0] = 0.f; c3[mt][1] = 0.f; c3[mt][2] = 0.f; c3[mt][3] = 0.f; }
#pragma unroll
            for (int ktl = 0; ktl < 4; ktl++) {
                uint32_t b0r, b1r;
                asm volatile("ldmatrix.sync.aligned.m8n8.x2.trans.shared.b16 {%0,%1}, [%2];\n"
                             : "=r"(b0r), "=r"(b1r)
                             : "r"(wb3 + (uint32_t)(sub * 4 + ktl) * 256));
                mma_16816(c3[0], hown[0][ktl][0], hown[0][ktl][1], hown[0][ktl][2], hown[0][ktl][3], b0r, b1r);
                mma_16816(c3[1], hown[1][ktl][0], hown[1][ktl][1], hown[1][ktl][2], hown[1][ktl][3], b0r, b1r);
            }
            *(float4*)redw = make_float4(c3[1 - sub][0], c3[1 - sub][1], c3[1 - sub][2], c3[1 - sub][3]);
            asm volatile("bar.sync %0, 64;" :: "r"(barP) : "memory");
            float4 pr = *(const float4*)redr;
            float o0 = c3[sub][0] + pr.x;
            float o1 = c3[sub][1] + pr.y;
            float o2 = c3[sub][2] + pr.z;
            float o3 = c3[sub][3] + pr.w;

            int r = tile * TILE + pairP * 32 + sub * 16 + (lane >> 2);
            if (cb == 0) {
                out[r * 3 + 0] = o0 + bs[384];       out[r * 3 + 1] = o1 + bs[385];
                out[(r + 8) * 3 + 0] = o2 + bs[384]; out[(r + 8) * 3 + 1] = o3 + bs[385];
            } else if (cb == 2) {
                out[r * 3 + 2] = o0 + bs[386];
                out[(r + 8) * 3 + 2] = o2 + bs[386];
            }
        }
    } else {
        // ================= gather warps: precompute into regs, store after wait =================
        int gw = wid - 8;            // 0..3
        int hf = lane & 1;
        int psub = lane >> 1;        // 0..15
        int li = 0;
        for (int tile = blockIdx.x; tile < ntiles; tile += gridDim.x, li++) {
            int buf = li & 1;
            uint4 res[2][6];         // [pass][lod]
#pragma unroll
            for (int pass = 0; pass < 2; pass++) {
                int p = gw * 16 + psub + pass * 64;
                float2 g = coords[tile * TILE + p];
                float gx = (g.x + 1.f) * 0.5f;
                float gy = (g.y + 1.f) * 0.5f;
#pragma unroll
                for (int lod = 0; lod < 6; lod++) {
                    const int sl = 4 + lod;
                    const int s  = 1 << sl;
                    const float sm1 = (float)(s - 1);
                    float fx = fminf(fmaxf(gx * sm1, 0.f), sm1);
                    float fy = fminf(fmaxf(gy * sm1, 0.f), sm1);
                    float x0f = floorf(fx), y0f = floorf(fy);
                    int   x0 = (int)x0f, y0 = (int)y0f;
                    float wx = fx - x0f, wy = fy - y0f;
                    int   x1 = min(x0 + 1, s - 1);
                    int   y1 = min(y0 + 1, s - 1);
                    float w00 = (1.f - wx) * (1.f - wy), w10 = wx * (1.f - wy);
                    float w01 = (1.f - wx) * wy,         w11 = wx * wy;
                    const char* fmb = (const char*)g_fm + (hf << 4);
                    uint4 t00 = *(const uint4*)(fmb + ((uint32_t)(c_loff[lod] + ((y0 << sl) + x0)) << 5));
                    uint4 t10 = *(const uint4*)(fmb + ((uint32_t)(c_loff[lod] + ((y0 << sl) + x1)) << 5));
                    uint4 t01 = *(const uint4*)(fmb + ((uint32_t)(c_loff[lod] + ((y1 << sl) + x0)) << 5));
                    uint4 t11 = *(const uint4*)(fmb + ((uint32_t)(c_loff[lod] + ((y1 << sl) + x1)) << 5));
                    const __half2* h00 = reinterpret_cast<const __half2*>(&t00);
                    const __half2* h10 = reinterpret_cast<const __half2*>(&t10);
                    const __half2* h01 = reinterpret_cast<const __half2*>(&t01);
                    const __half2* h11 = reinterpret_cast<const __half2*>(&t11);
                    __half2* ro = reinterpret_cast<__half2*>(&res[pass][lod]);
#pragma unroll
                    for (int e = 0; e < 4; e++) {
                        float2 a = __half22float2(h00[e]);
                        float2 b = __half22float2(h10[e]);
                        float2 c = __half22float2(h01[e]);
                        float2 d = __half22float2(h11[e]);
                        float rx = a.x * w00 + b.x * w10 + c.x * w01 + d.x * w11;
                        float ry = a.y * w00 + b.y * w10 + c.y * w01 + d.y * w11;
                        ro[e] = __floats2half2_rn(rx, ry);
                    }
                }
            }
            // only NOW wait for the buffer — the store phase is cheap
            if (li >= 2)
                asm volatile("bar.sync %0, 384;" :: "r"(4 + buf) : "memory");
            __half* a0 = act0 + buf * (128 * A0STRIDE);
#pragma unroll
            for (int pass = 0; pass < 2; pass++) {
                int p = gw * 16 + psub + pass * 64;
#pragma unroll
                for (int lod = 0; lod < 6; lod++)
                    *reinterpret_cast<uint4*>(a0 + p * A0STRIDE + lod * 16 + hf * 8) = res[pass][lod];
            }
            asm volatile("bar.arrive %0, 384;" :: "r"(2 + buf) : "memory");
        }
    }
}

// =====================================================================
extern "C" void kernel_launch(void* const* d_in, const int* in_sizes, int n_in,
                              void* d_out, int out_size)
{
    const float* xc = (const float*)d_in[0];
    const float* f0 = (const float*)d_in[1];
    const float* f1 = (const float*)d_in[2];
    const float* f2 = (const float*)d_in[3];
    const float* f3 = (const float*)d_in[4];
    const float* f4 = (const float*)d_in[5];
    const float* f5 = (const float*)d_in[6];
    const float* lg = (const float*)d_in[7];
    const float* w0 = (const float*)d_in[8];
    const float* b0 = (const float*)d_in[9];
    const float* w1 = (const float*)d_in[10];
    const float* b1 = (const float*)d_in[11];
    const float* w2 = (const float*)d_in[12];
    const float* b2 = (const float*)d_in[13];
    const float* w3 = (const float*)d_in[14];
    const float* b3 = (const float*)d_in[15];

    int npts   = in_sizes[0] / 2;
    int ntiles = npts / TILE;              // 8192 for 1024x1024

    prep_all<<<(349440 + 46080 + 255) / 256, 256>>>(f0, f1, f2, f3, f4, f5, lg, w0, w1, w2, w3);

    cudaFuncSetAttribute(enc_main, cudaFuncAttributeMaxDynamicSharedMemorySize, SMEM_BYTES);
    int nsm = 0;
    cudaDeviceGetAttribute(&nsm, cudaDevAttrMultiProcessorCount, 0);
    if (nsm <= 0) nsm = 148;

    enc_main<<<nsm, THREADS, SMEM_BYTES>>>(
        (const float2*)xc, b0, b1, b2, b3, (float*)d_out, ntiles);
}

// round 17
// speedup vs baseline: 1.2548x; 1.1448x over previous
#include <cuda_runtime.h>
#include <cuda_fp16.h>
#include <stdint.h>

#define THREADS  384
#define HTILE    64    // points per half-pipeline tile
#define A0STRIDE 104   // feature tile row stride in halves (208B = 13*16B, conflict-free ldmatrix)

// -------- device-global scratch --------
__device__ __half g_fm[349440 * 16];    // interleaved [texel][16] fp16, gain folded (11.2 MB)
__device__ __half g_w0[96 * 128];       // [k][n] fp16, 16B-chunk XOR-swizzled
__device__ __half g_w1[128 * 128];
__device__ __half g_w2[128 * 128];
__device__ __half g_w3[128 * 8];        // linear, cols 3..7 zero-padded

__constant__ int c_loff[6] = {0, 256, 1280, 5376, 21760, 87296};

__device__ __forceinline__ int wswz(int k, int n) {
    return k * 128 + ((((n >> 3) ^ (k & 7))) << 3) + (n & 7);
}

// =====================================================================
// Prep kernel: fm interleave (fp16) + weight transpose/swizzle
// =====================================================================
__global__ void prep_all(const float* __restrict__ f0, const float* __restrict__ f1,
                         const float* __restrict__ f2, const float* __restrict__ f3,
                         const float* __restrict__ f4, const float* __restrict__ f5,
                         const float* __restrict__ lg,
                         const float* __restrict__ w0, const float* __restrict__ w1,
                         const float* __restrict__ w2, const float* __restrict__ w3)
{
    int idx = blockIdx.x * blockDim.x + threadIdx.x;
    if (idx < 349440) {
        int tex = idx;
        int lod; const float* f;
        if      (tex < 256)   { lod = 0; f = f0; }
        else if (tex < 1280)  { lod = 1; f = f1; }
        else if (tex < 5376)  { lod = 2; f = f2; }
        else if (tex < 21760) { lod = 3; f = f3; }
        else if (tex < 87296) { lod = 4; f = f4; }
        else                  { lod = 5; f = f5; }
        int local = tex - c_loff[lod];
        int ss = 1 << (2 * (4 + lod));
        float gain = exp2f(lg[lod]);
        __half h[16];
#pragma unroll
        for (int c = 0; c < 16; c++) h[c] = __float2half(f[c * ss + local] * gain);
        uint4* dst = reinterpret_cast<uint4*>(g_fm + tex * 16);
        dst[0] = *reinterpret_cast<uint4*>(&h[0]);
        dst[1] = *reinterpret_cast<uint4*>(&h[8]);
        return;
    }
    int i = idx - 349440;
    if (i < 12288) {                         // w0: 96x128 (k x n)
        int n = i & 127, k = i >> 7;
        g_w0[wswz(k, n)] = __float2half(w0[n * 96 + k]);
    } else if (i < 28672) {                  // w1
        int j = i - 12288;
        int n = j & 127, k = j >> 7;
        g_w1[wswz(k, n)] = __float2half(w1[n * 128 + k]);
    } else if (i < 45056) {                  // w2
        int j = i - 28672;
        int n = j & 127, k = j >> 7;
        g_w2[wswz(k, n)] = __float2half(w2[n * 128 + k]);
    } else if (i < 46080) {                  // w3: 128x8, linear, n>=3 zero
        int j = i - 45056;
        int n = j & 7, k = j >> 3;
        g_w3[j] = (n < 3) ? __float2half(w3[n * 128 + k]) : __float2half(0.f);
    }
}

// =====================================================================
__device__ __forceinline__ uint32_t smem_u32(const void* p) {
    return (uint32_t)__cvta_generic_to_shared(p);
}

__device__ __forceinline__ void mma_16816(float* c, uint32_t a0, uint32_t a1, uint32_t a2, uint32_t a3,
                                          uint32_t b0, uint32_t b1) {
    asm volatile(
        "mma.sync.aligned.m16n8k16.row.col.f32.f16.f16.f32 "
        "{%0,%1,%2,%3},{%4,%5,%6,%7},{%8,%9},{%0,%1,%2,%3};\n"
        : "+f"(c[0]), "+f"(c[1]), "+f"(c[2]), "+f"(c[3])
        : "r"(a0), "r"(a1), "r"(a2), "r"(a3), "r"(b0), "r"(b1));
}

__device__ __forceinline__ uint32_t pack_relu(float x, float y) {
    __half2 h = __floats2half2_rn(fmaxf(x, 0.f), fmaxf(y, 0.f));
    return *reinterpret_cast<uint32_t*>(&h);
}

__device__ __forceinline__ void sts_u32(uint32_t addr, uint32_t v) {
    asm volatile("st.shared.u32 [%0], %1;" :: "r"(addr), "r"(v) : "memory");
}

// ---------------- SMEM layout (bytes) ----------------
// act0: [half][buf][64][104] halves = 2*2*64*104*2 = 53248
// exch: [half][laybuf][2 pairs][32][136] halves = 2*2*17408 = 69632
#define S_ACT0  0
#define S_EXCH  53248
#define EXBUF_H 17408                    // one exchange buffer per half (2 pairs)
#define S_W     122880                   // 92160
#define S_BIAS  215040                   // 392 floats
#define SMEM_BYTES (215040 + 1600)
#define EXROW    272                     // exchange row stride bytes (136 halves)

// =====================================================================
// TWO independent tile pipelines per block (half h = 0,1), each:
//   2 MLP pairs (4 warps) on 64-pt tiles + 2 gather warps.
// Warps 0-3: MLP h0 | 4-7: MLP h1 | 8-9: gather h0 | 10-11: gather h1.
// Per-SMSP: one MLP warp from each half + one gather warp -> cross-half overlap.
// Barriers: half h full[b]=2+4h+b, empty[b]=4+4h+b (count 192); pair: 10+2h+P (count 64).
// =====================================================================
__global__ void __launch_bounds__(THREADS, 1) enc_main(
    const float2* __restrict__ coords,
    const float* __restrict__ b0, const float* __restrict__ b1,
    const float* __restrict__ b2, const float* __restrict__ b3,
    float* __restrict__ out, int ntiles64)
{
    extern __shared__ __align__(16) char sm[];
    __half* act0 = reinterpret_cast<__half*>(sm + S_ACT0);
    __half* w0s  = reinterpret_cast<__half*>(sm + S_W);
    __half* w1s  = w0s + 12288;
    __half* w2s  = w1s + 16384;
    __half* w3s  = w2s + 16384;
    float*  bs   = reinterpret_cast<float*>(sm + S_BIAS);

    int tid = threadIdx.x;

    // ---- stage weights + biases ----
    {
        uint4* dw = (uint4*)w0s;
        const uint4* s0 = (const uint4*)g_w0;
        for (int i = tid; i < 12288 / 8; i += THREADS) dw[i] = s0[i];
        const uint4* s1 = (const uint4*)g_w1;
        for (int i = tid; i < 16384 / 8; i += THREADS) dw[1536 + i] = s1[i];
        const uint4* s2 = (const uint4*)g_w2;
        for (int i = tid; i < 16384 / 8; i += THREADS) dw[3584 + i] = s2[i];
        const uint4* s3 = (const uint4*)g_w3;
        for (int i = tid; i < 1024 / 8;  i += THREADS) dw[5632 + i] = s3[i];
        for (int i = tid; i < 128; i += THREADS) {
            bs[i] = b0[i]; bs[128 + i] = b1[i]; bs[256 + i] = b2[i];
        }
        if (tid < 8) bs[384 + tid] = (tid < 3) ? b3[tid] : 0.f;
    }
    __syncthreads();

    int wid = tid >> 5, lane = tid & 31;

    if (wid < 8) {
        // ================= MLP warps: half = wid>>2, pair = (wid>>1)&1, sub = wid&1 =====
        const int h     = wid >> 2;
        const int pairP = (wid >> 1) & 1;
        const int sub   = wid & 1;
        const int cb = (lane & 3) * 2;
        const int cp = lane >> 4;
        const int xorv = lane & 7;
        const int nbase = sub * 64;
        uint32_t wb0 = smem_u32(w0s) + ((lane & 15) << 8);
        uint32_t wb1 = smem_u32(w1s) + ((lane & 15) << 8);
        uint32_t wb2 = smem_u32(w2s) + ((lane & 15) << 8);
        uint32_t wb3 = smem_u32(w3s) + ((lane & 15) << 4);
        uint32_t exch_h = smem_u32(sm + S_EXCH) + (uint32_t)h * (2 * EXBUF_H);
        uint32_t exch_b = exch_h + pairP * (32 * EXROW);
        uint32_t stsb = exch_b + (lane >> 2) * EXROW + sub * 128 + cb * 2;
        uint32_t prdb = exch_b + (lane & 15) * EXROW + (1 - sub) * 128 + ((lane >> 4) << 4);
        const uint32_t kofs_own  = (uint32_t)sub << 14;
        const uint32_t kofs_part = (uint32_t)(1 - sub) << 14;
        const int barP   = 10 + h * 2 + pairP;
        const int barFull0 = 2 + h * 4, barEmpty0 = 4 + h * 4;
        float* redw = (float*)(void*)(uintptr_t)0;  // computed below via generic ptr
        float* redr;
        {
            char* exg = sm + S_EXCH + h * (2 * EXBUF_H) + pairP * (32 * EXROW);
            redw = (float*)(exg + (1 - sub) * (16 * EXROW)) + lane * 4;
            redr = (float*)(exg + sub       * (16 * EXROW)) + lane * 4;
        }

        float    c[2][8][4];        // [mt][n8 within n64][frag]
        uint32_t hown[2][4][4];     // own k-half A frags

        int li = 0;
        for (int tile = blockIdx.x * 2 + h; tile < ntiles64; tile += 2 * gridDim.x, li++) {
            int buf = li & 1;
            asm volatile("bar.sync %0, 192;" :: "r"(barFull0 + buf) : "memory");
            const __half* a0 = act0 + (h * 2 + buf) * (HTILE * A0STRIDE);
            uint32_t ab = smem_u32(a0 + (pairP * 32 + (lane & 15)) * A0STRIDE) + ((lane >> 4) << 4);

            // ---------- layer 0: 96 -> 128 ----------
#pragma unroll
            for (int n8 = 0; n8 < 8; n8++) {
                float2 bv = *reinterpret_cast<const float2*>(bs + nbase + n8 * 8 + cb);
#pragma unroll
                for (int mt = 0; mt < 2; mt++) {
                    c[mt][n8][0] = bv.x; c[mt][n8][1] = bv.y;
                    c[mt][n8][2] = bv.x; c[mt][n8][3] = bv.y;
                }
            }
#pragma unroll
            for (int kt = 0; kt < 6; kt++) {
                uint32_t A[2][4];
#pragma unroll
                for (int mt = 0; mt < 2; mt++)
                    asm volatile("ldmatrix.sync.aligned.m8n8.x4.shared.b16 {%0,%1,%2,%3}, [%4];\n"
                                 : "=r"(A[mt][0]), "=r"(A[mt][1]), "=r"(A[mt][2]), "=r"(A[mt][3])
                                 : "r"(ab + mt * (16 * A0STRIDE * 2) + kt * 32));
#pragma unroll
                for (int j = 0; j < 4; j++) {
                    int chunk = sub * 8 + 2 * j + cp;
                    uint32_t baddr = wb0 + (kt << 12) + ((uint32_t)(chunk ^ xorv) << 4);
                    uint32_t b[4];
                    asm volatile("ldmatrix.sync.aligned.m8n8.x4.trans.shared.b16 {%0,%1,%2,%3}, [%4];\n"
                                 : "=r"(b[0]), "=r"(b[1]), "=r"(b[2]), "=r"(b[3]) : "r"(baddr));
#pragma unroll
                    for (int mt = 0; mt < 2; mt++) {
                        mma_16816(c[mt][2 * j + 0], A[mt][0], A[mt][1], A[mt][2], A[mt][3], b[0], b[1]);
                        mma_16816(c[mt][2 * j + 1], A[mt][0], A[mt][1], A[mt][2], A[mt][3], b[2], b[3]);
                    }
                }
            }
            asm volatile("bar.arrive %0, 192;" :: "r"(barEmpty0 + buf) : "memory");

            // ---------- layers 1,2: own-half mma BEFORE barrier, partner streamed after ----------
#pragma unroll 1
            for (int layer = 1; layer <= 2; layer++) {
                const uint32_t eoff = (uint32_t)(layer - 1) * EXBUF_H;
#pragma unroll
                for (int mt = 0; mt < 2; mt++)
#pragma unroll
                    for (int t = 0; t < 4; t++) {
                        uint32_t v0 = pack_relu(c[mt][2 * t][0],     c[mt][2 * t][1]);
                        uint32_t v1 = pack_relu(c[mt][2 * t][2],     c[mt][2 * t][3]);
                        uint32_t v2 = pack_relu(c[mt][2 * t + 1][0], c[mt][2 * t + 1][1]);
                        uint32_t v3 = pack_relu(c[mt][2 * t + 1][2], c[mt][2 * t + 1][3]);
                        hown[mt][t][0] = v0; hown[mt][t][1] = v1;
                        hown[mt][t][2] = v2; hown[mt][t][3] = v3;
                        uint32_t sa = stsb + eoff + mt * (16 * EXROW) + t * 32;
                        sts_u32(sa, v0);
                        sts_u32(sa + 8 * EXROW, v1);
                        sts_u32(sa + 16, v2);
                        sts_u32(sa + 8 * EXROW + 16, v3);
                    }
                const float* bias = bs + layer * 128;
                uint32_t wb = (layer == 1) ? wb1 : wb2;
#pragma unroll
                for (int n8 = 0; n8 < 8; n8++) {
                    float2 bv = *reinterpret_cast<const float2*>(bias + nbase + n8 * 8 + cb);
#pragma unroll
                    for (int mt = 0; mt < 2; mt++) {
                        c[mt][n8][0] = bv.x; c[mt][n8][1] = bv.y;
                        c[mt][n8][2] = bv.x; c[mt][n8][3] = bv.y;
                    }
                }
                // own k-half (registers) — hides partner's STS
#pragma unroll
                for (int ktl = 0; ktl < 4; ktl++) {
#pragma unroll
                    for (int j = 0; j < 4; j++) {
                        int chunk = sub * 8 + 2 * j + cp;
                        uint32_t cofs = (uint32_t)(chunk ^ xorv) << 4;
                        uint32_t b[4];
                        asm volatile("ldmatrix.sync.aligned.m8n8.x4.trans.shared.b16 {%0,%1,%2,%3}, [%4];\n"
                                     : "=r"(b[0]), "=r"(b[1]), "=r"(b[2]), "=r"(b[3])
                                     : "r"(wb + kofs_own + (ktl << 12) + cofs));
#pragma unroll
                        for (int mt = 0; mt < 2; mt++) {
                            mma_16816(c[mt][2 * j + 0], hown[mt][ktl][0], hown[mt][ktl][1], hown[mt][ktl][2], hown[mt][ktl][3], b[0], b[1]);
                            mma_16816(c[mt][2 * j + 1], hown[mt][ktl][0], hown[mt][ktl][1], hown[mt][ktl][2], hown[mt][ktl][3], b[2], b[3]);
                        }
                    }
                }
                asm volatile("bar.sync %0, 64;" :: "r"(barP) : "memory");
                // partner k-half: per-ktl temporaries
#pragma unroll
                for (int ktl = 0; ktl < 4; ktl++) {
                    uint32_t hp0[4], hp1[4];
                    asm volatile("ldmatrix.sync.aligned.m8n8.x4.shared.b16 {%0,%1,%2,%3}, [%4];\n"
                                 : "=r"(hp0[0]), "=r"(hp0[1]), "=r"(hp0[2]), "=r"(hp0[3])
                                 : "r"(prdb + eoff + ktl * 32));
                    asm volatile("ldmatrix.sync.aligned.m8n8.x4.shared.b16 {%0,%1,%2,%3}, [%4];\n"
                                 : "=r"(hp1[0]), "=r"(hp1[1]), "=r"(hp1[2]), "=r"(hp1[3])
                                 : "r"(prdb + eoff + 16 * EXROW + ktl * 32));
#pragma unroll
                    for (int j = 0; j < 4; j++) {
                        int chunk = sub * 8 + 2 * j + cp;
                        uint32_t cofs = (uint32_t)(chunk ^ xorv) << 4;
                        uint32_t b[4];
                        asm volatile("ldmatrix.sync.aligned.m8n8.x4.trans.shared.b16 {%0,%1,%2,%3}, [%4];\n"
                                     : "=r"(b[0]), "=r"(b[1]), "=r"(b[2]), "=r"(b[3])
                                     : "r"(wb + kofs_part + (ktl << 12) + cofs));
                        mma_16816(c[0][2 * j + 0], hp0[0], hp0[1], hp0[2], hp0[3], b[0], b[1]);
                        mma_16816(c[0][2 * j + 1], hp0[0], hp0[1], hp0[2], hp0[3], b[2], b[3]);
                        mma_16816(c[1][2 * j + 0], hp1[0], hp1[1], hp1[2], hp1[3], b[0], b[1]);
                        mma_16816(c[1][2 * j + 1], hp1[0], hp1[1], hp1[2], hp1[3], b[2], b[3]);
                    }
                }
            }

            // ---------- out layer: partial-k for BOTH m-tiles + pair reduction ----------
#pragma unroll
            for (int mt = 0; mt < 2; mt++)
#pragma unroll
                for (int t = 0; t < 4; t++) {
                    hown[mt][t][0] = pack_relu(c[mt][2 * t][0],     c[mt][2 * t][1]);
                    hown[mt][t][1] = pack_relu(c[mt][2 * t][2],     c[mt][2 * t][3]);
                    hown[mt][t][2] = pack_relu(c[mt][2 * t + 1][0], c[mt][2 * t + 1][1]);
                    hown[mt][t][3] = pack_relu(c[mt][2 * t + 1][2], c[mt][2 * t + 1][3]);
                }
            float c3[2][4];
#pragma unroll
            for (int mt = 0; mt < 2; mt++) { c3[mt][0] = 0.f; c3[mt][1] = 0.f; c3[mt][2] = 0.f; c3[mt][3] = 0.f; }
#pragma unroll
            for (int ktl = 0; ktl < 4; ktl++) {
                uint32_t b0r, b1r;
                asm volatile("ldmatrix.sync.aligned.m8n8.x2.trans.shared.b16 {%0,%1}, [%2];\n"
                             : "=r"(b0r), "=r"(b1r)
                             : "r"(wb3 + (uint32_t)(sub * 4 + ktl) * 256));
                mma_16816(c3[0], hown[0][ktl][0], hown[0][ktl][1], hown[0][ktl][2], hown[0][ktl][3], b0r, b1r);
                mma_16816(c3[1], hown[1][ktl][0], hown[1][ktl][1], hown[1][ktl][2], hown[1][ktl][3], b0r, b1r);
            }
            *(float4*)redw = make_float4(c3[1 - sub][0], c3[1 - sub][1], c3[1 - sub][2], c3[1 - sub][3]);
            asm volatile("bar.sync %0, 64;" :: "r"(barP) : "memory");
            float4 pr = *(const float4*)redr;
            float o0 = c3[sub][0] + pr.x;
            float o1 = c3[sub][1] + pr.y;
            float o2 = c3[sub][2] + pr.z;
            float o3 = c3[sub][3] + pr.w;

            int r = tile * HTILE + pairP * 32 + sub * 16 + (lane >> 2);
            if (cb == 0) {
                out[r * 3 + 0] = o0 + bs[384];       out[r * 3 + 1] = o1 + bs[385];
                out[(r + 8) * 3 + 0] = o2 + bs[384]; out[(r + 8) * 3 + 1] = o3 + bs[385];
            } else if (cb == 2) {
                out[r * 3 + 2] = o0 + bs[386];
                out[(r + 8) * 3 + 2] = o2 + bs[386];
            }
        }
    } else {
        // ================= gather warps: half = (wid-8)>>1, gwarp = (wid-8)&1 =========
        const int h  = (wid - 8) >> 1;
        const int gw = (wid - 8) & 1;
        const int hf = lane & 1;
        const int psub = lane >> 1;        // 0..15
        const int barFull0 = 2 + h * 4, barEmpty0 = 4 + h * 4;
        int li = 0;
        for (int tile = blockIdx.x * 2 + h; tile < ntiles64; tile += 2 * gridDim.x, li++) {
            int buf = li & 1;
            if (li >= 2)
                asm volatile("bar.sync %0, 192;" :: "r"(barEmpty0 + buf) : "memory");
            __half* a0 = act0 + (h * 2 + buf) * (HTILE * A0STRIDE);

#pragma unroll
            for (int pass = 0; pass < 2; pass++) {
                int p = gw * 16 + psub + pass * 32;     // 0..63 within half-tile
                float2 g = coords[tile * HTILE + p];
                float gx = (g.x + 1.f) * 0.5f;
                float gy = (g.y + 1.f) * 0.5f;
#pragma unroll
                for (int lod = 0; lod < 6; lod++) {
                    const int sl = 4 + lod;
                    const int s  = 1 << sl;
                    const float sm1 = (float)(s - 1);
                    float fx = fminf(fmaxf(gx * sm1, 0.f), sm1);
                    float fy = fminf(fmaxf(gy * sm1, 0.f), sm1);
                    float x0f = floorf(fx), y0f = floorf(fy);
                    int   x0 = (int)x0f, y0 = (int)y0f;
                    float wx = fx - x0f, wy = fy - y0f;
                    int   x1 = min(x0 + 1, s - 1);
                    int   y1 = min(y0 + 1, s - 1);
                    float w00 = (1.f - wx) * (1.f - wy), w10 = wx * (1.f - wy);
                    float w01 = (1.f - wx) * wy,         w11 = wx * wy;
                    const char* fmb = (const char*)g_fm + (hf << 4);
                    uint4 t00 = *(const uint4*)(fmb + ((uint32_t)(c_loff[lod] + ((y0 << sl) + x0)) << 5));
                    uint4 t10 = *(const uint4*)(fmb + ((uint32_t)(c_loff[lod] + ((y0 << sl) + x1)) << 5));
                    uint4 t01 = *(const uint4*)(fmb + ((uint32_t)(c_loff[lod] + ((y1 << sl) + x0)) << 5));
                    uint4 t11 = *(const uint4*)(fmb + ((uint32_t)(c_loff[lod] + ((y1 << sl) + x1)) << 5));
                    const __half2* h00 = reinterpret_cast<const __half2*>(&t00);
                    const __half2* h10 = reinterpret_cast<const __half2*>(&t10);
                    const __half2* h01 = reinterpret_cast<const __half2*>(&t01);
                    const __half2* h11 = reinterpret_cast<const __half2*>(&t11);
                    uint4 res;
                    __half2* ro = reinterpret_cast<__half2*>(&res);
#pragma unroll
                    for (int e = 0; e < 4; e++) {
                        float2 a = __half22float2(h00[e]);
                        float2 b = __half22float2(h10[e]);
                        float2 c = __half22float2(h01[e]);
                        float2 d = __half22float2(h11[e]);
                        float rx = a.x * w00 + b.x * w10 + c.x * w01 + d.x * w11;
                        float ry = a.y * w00 + b.y * w10 + c.y * w01 + d.y * w11;
                        ro[e] = __floats2half2_rn(rx, ry);
                    }
                    *reinterpret_cast<uint4*>(a0 + p * A0STRIDE + lod * 16 + hf * 8) = res;
                }
            }
            asm volatile("bar.arrive %0, 192;" :: "r"(barFull0 + buf) : "memory");
        }
    }
}

// =====================================================================
extern "C" void kernel_launch(void* const* d_in, const int* in_sizes, int n_in,
                              void* d_out, int out_size)
{
    const float* xc = (const float*)d_in[0];
    const float* f0 = (const float*)d_in[1];
    const float* f1 = (const float*)d_in[2];
    const float* f2 = (const float*)d_in[3];
    const float* f3 = (const float*)d_in[4];
    const float* f4 = (const float*)d_in[5];
    const float* f5 = (const float*)d_in[6];
    const float* lg = (const float*)d_in[7];
    const float* w0 = (const float*)d_in[8];
    const float* b0 = (const float*)d_in[9];
    const float* w1 = (const float*)d_in[10];
    const float* b1 = (const float*)d_in[11];
    const float* w2 = (const float*)d_in[12];
    const float* b2 = (const float*)d_in[13];
    const float* w3 = (const float*)d_in[14];
    const float* b3 = (const float*)d_in[15];

    int npts     = in_sizes[0] / 2;
    int ntiles64 = npts / HTILE;           // 16384 for 1024x1024

    prep_all<<<(349440 + 46080 + 255) / 256, 256>>>(f0, f1, f2, f3, f4, f5, lg, w0, w1, w2, w3);

    cudaFuncSetAttribute(enc_main, cudaFuncAttributeMaxDynamicSharedMemorySize, SMEM_BYTES);
    int nsm = 0;
    cudaDeviceGetAttribute(&nsm, cudaDevAttrMultiProcessorCount, 0);
    if (nsm <= 0) nsm = 148;

    enc_main<<<nsm, THREADS, SMEM_BYTES>>>(
        (const float2*)xc, b0, b1, b2, b3, (float*)d_out, ntiles64);
}